// round 1
// baseline (speedup 1.0000x reference)
#include <cuda_runtime.h>
#include <cstdint>

// Problem: per-row top-k (k=64) of x[16384, 8192] fp32, scattered back densely
// (non-top-k positions = 0). Exact tie semantics of jax.lax.top_k (lowest index
// wins among equal values).
//
// Strategy: one 256-thread CTA per row. Row lives in registers (32 elems/thread,
// loaded as 8x float4, coalesced). Exact k-th-largest via 4-round 8-bit radix
// select on monotone float->uint keys (shared histogram + parallel suffix scan).
// Ties at the threshold resolved exactly via a block-wide binary search over
// element indices (rare path). Single read of x, single write of out: 1 GiB
// total traffic -> HBM-bound.

#define TPB   256
#define COLS  8192
#define VPT   8            // float4 per thread
#define EPT   32           // elements per thread

__device__ __forceinline__ uint32_t f2key(float f) {
    uint32_t u = __float_as_uint(f);
    // monotone ascending: larger float -> larger key
    return u ^ ((u & 0x80000000u) ? 0xFFFFFFFFu : 0x80000000u);
}

__device__ __forceinline__ float key2f(uint32_t k) {
    uint32_t u = (k & 0x80000000u) ? (k ^ 0x80000000u) : ~k;
    return __uint_as_float(u);
}

__global__ void __launch_bounds__(TPB)
topk_scatter_kernel(const float* __restrict__ x,
                    const unsigned int* __restrict__ kp,
                    float* __restrict__ out)
{
    const int row = blockIdx.x;
    const int t   = threadIdx.x;

    const float4* __restrict__ xr   = reinterpret_cast<const float4*>(x + (size_t)row * COLS);
    float4* __restrict__       orow = reinterpret_cast<float4*>(out + (size_t)row * COLS);

    // ---- Load row into registers as radix keys (coalesced LDG.128) ----
    uint32_t key[EPT];
#pragma unroll
    for (int j = 0; j < VPT; j++) {
        float4 v = __ldg(&xr[t + j * TPB]);
        key[4*j + 0] = f2key(v.x);
        key[4*j + 1] = f2key(v.y);
        key[4*j + 2] = f2key(v.z);
        key[4*j + 3] = f2key(v.w);
    }

    __shared__ uint32_t hist[256];
    __shared__ uint32_t sh_sel, sh_hi, sh_e, sh_cnt;

    // k input (defensive: accept int32/int64 little-endian; fall back to 64)
    uint32_t K = 64u;
    if (kp) {
        uint32_t raw = __ldg(kp);
        if (raw >= 1u && raw <= (uint32_t)COLS) {
            K = raw;
        } else {
            float f = __uint_as_float(raw);
            if (f >= 1.0f && f <= (float)COLS) K = (uint32_t)f;
        }
    }

    // ---- 4-round radix select: find the K-th largest 32-bit key exactly ----
    uint32_t kk = K;          // remaining rank within current candidate set
    uint32_t prefix = 0;      // resolved high bits of the threshold key

#pragma unroll
    for (int round = 0; round < 4; round++) {
        const int shift = 24 - 8 * round;
        hist[t] = 0u;
        __syncthreads();

        const uint32_t pmask = (round == 0) ? 0u : (0xFFFFFFFFu << (shift + 8));
        const uint32_t phi   = (round == 0) ? 0u : (prefix << (shift + 8));

#pragma unroll
        for (int e = 0; e < EPT; e++) {
            uint32_t kv = key[e];
            if ((kv & pmask) == phi)
                atomicAdd(&hist[(kv >> shift) & 0xFFu], 1u);
        }
        __syncthreads();

        // Parallel suffix scan: hist[d] := sum_{j>=d} hist[j]
        for (int off = 1; off < 256; off <<= 1) {
            uint32_t v = hist[t];
            uint32_t w = (t + off < 256) ? hist[t + off] : 0u;
            __syncthreads();
            hist[t] = v + w;
            __syncthreads();
        }

        // Pick the bin containing the kk-th largest: largest d with S[d] >= kk
        uint32_t S     = hist[t];
        uint32_t Snext = (t < 255) ? hist[t + 1] : 0u;
        if (S >= kk && Snext < kk) {
            sh_sel = (uint32_t)t;   // selected digit
            sh_hi  = Snext;         // count of keys strictly above this bin
            sh_e   = S - Snext;     // count of keys inside this bin
        }
        __syncthreads();

        prefix = (prefix << 8) | sh_sel;
        kk    -= sh_hi;
        // next round's "hist[t]=0; __syncthreads()" orders sh_* reuse safely
    }

    const uint32_t thresh = prefix;   // exact K-th largest key
    const uint32_t keep   = kk;       // how many threshold-equal elements to keep
    const uint32_t neq    = sh_e;     // total threshold-equal elements (>= keep >= 1)

    // ---- Tie resolution (exact jax.lax.top_k semantics: lowest index first) ----
    int t_idx = COLS - 1;             // keep equals with index <= t_idx
    if (neq > keep) {
        // binary search smallest m with count(key==thresh && idx<=m) >= keep
        int lo = 0, hi = COLS - 1;
        while (lo < hi) {
            int mid = (lo + hi) >> 1;
            if (t == 0) sh_cnt = 0u;
            __syncthreads();
            uint32_t local = 0;
#pragma unroll
            for (int j = 0; j < VPT; j++) {
                int base = 4 * (t + j * TPB);
#pragma unroll
                for (int c = 0; c < 4; c++) {
                    if (key[4*j + c] == thresh && (base + c) <= mid) local++;
                }
            }
            if (local) atomicAdd(&sh_cnt, local);
            __syncthreads();
            if (sh_cnt >= keep) hi = mid; else lo = mid + 1;
            __syncthreads();
        }
        t_idx = lo;
    }

    // ---- Write output (coalesced STG.128), reconstruct floats from keys ----
#pragma unroll
    for (int j = 0; j < VPT; j++) {
        const int base = 4 * (t + j * TPB);
        float4 o;
        {
            uint32_t kv = key[4*j + 0];
            o.x = (kv > thresh || (kv == thresh && (base + 0) <= t_idx)) ? key2f(kv) : 0.0f;
        }
        {
            uint32_t kv = key[4*j + 1];
            o.y = (kv > thresh || (kv == thresh && (base + 1) <= t_idx)) ? key2f(kv) : 0.0f;
        }
        {
            uint32_t kv = key[4*j + 2];
            o.z = (kv > thresh || (kv == thresh && (base + 2) <= t_idx)) ? key2f(kv) : 0.0f;
        }
        {
            uint32_t kv = key[4*j + 3];
            o.w = (kv > thresh || (kv == thresh && (base + 3) <= t_idx)) ? key2f(kv) : 0.0f;
        }
        orow[t + j * TPB] = o;
    }
}

extern "C" void kernel_launch(void* const* d_in, const int* in_sizes, int n_in,
                              void* d_out, int out_size)
{
    const float* x = (const float*)d_in[0];
    const unsigned int* kp = (n_in >= 2) ? (const unsigned int*)d_in[1] : nullptr;

    int rows = out_size / COLS;   // 16384 for this problem
    topk_scatter_kernel<<<rows, TPB>>>(x, kp, (float*)d_out);
}